// round 14
// baseline (speedup 1.0000x reference)
#include <cuda_runtime.h>
#include <cuda_fp16.h>
#include <cstdint>

#define NN 50000
#define EE 640000
#define DD 128          // feature dim (GEMM K)
#define KK 256          // W row length (2*DD)
#define DOUT 128
#define CAP 80          // max neighbors per node (Poisson(12.8): P(>=80) ~ 1e-45)

// ---------------- scratch (static device globals; no allocation) -------------
__device__ __half g_Yh[(size_t)NN * DD];    // x @ W1^T   fp16 (12.8 MB)
__device__ __half g_Z[(size_t)NN * DD];     // x @ W2^T   fp16 (12.8 MB)
__device__ int    g_bucket[(size_t)NN * CAP];  // adjacency buckets (16 MB)
__device__ int    g_cnt[NN];
// fp16 operands
__device__ __half g_xh[(size_t)NN * DD];    // x in fp16 (12.8 MB)
__device__ __half g_wh[DOUT * KK];          // W in fp16

// ---------------- 0) zero counters -------------------------------------------
__global__ void zero_kernel() {
    int i = blockIdx.x * blockDim.x + threadIdx.x;
    if (i < NN) g_cnt[i] = 0;
}

// ---------------- 1) decode edge index + bucket insert (fused) ----------------
__global__ void decode_bucket_kernel(const void* __restrict__ ei) {
    const int* ei32 = (const int*)ei;
    int t = threadIdx.x;
    int accw = ei32[2 * t + 1] | ei32[2 * (t + 256) + 1];
    int is32 = __syncthreads_or(accw);      // nonzero -> int32 indices

    int e = blockIdx.x * blockDim.x + t;
    if (e >= EE) return;
    int r, c;
    if (!is32) {
        const long long* p = (const long long*)ei;
        r = (int)p[e];
        c = (int)p[(size_t)EE + e];
    } else {
        r = ei32[e];
        c = ei32[EE + e];
    }
    r = min(max(r, 0), NN - 1);
    c = min(max(c, 0), NN - 1);
    int slot = atomicAdd(&g_cnt[r], 1);
    if (slot < CAP)
        g_bucket[(size_t)r * CAP + slot] = c;
}

// ---------------- 2) one-pass fp16 convert of x and W -------------------------
#define NX4 ((NN * DD) / 4)
#define NW4 ((DOUT * KK) / 4)
__global__ void split_kernel(const float* __restrict__ x, const float* __restrict__ W) {
    int i = blockIdx.x * blockDim.x + threadIdx.x;
    if (i < NX4) {
        float4 v = ((const float4*)x)[i];
        __half2 h01 = __floats2half2_rn(v.x, v.y);
        __half2 h23 = __floats2half2_rn(v.z, v.w);
        uint2 pk;
        pk.x = *(uint32_t*)&h01;
        pk.y = *(uint32_t*)&h23;
        *(uint2*)(g_xh + (size_t)i * 4) = pk;
    } else if (i < NX4 + NW4) {
        int j = i - NX4;
        float4 v = ((const float4*)W)[j];
        __half2 h01 = __floats2half2_rn(v.x, v.y);
        __half2 h23 = __floats2half2_rn(v.z, v.w);
        uint2 pk;
        pk.x = *(uint32_t*)&h01;
        pk.y = *(uint32_t*)&h23;
        *(uint2*)(g_wh + (size_t)j * 4) = pk;
    }
}

// ---------------- 3) GEMM: fp16 mma.sync, full-K prefetch, Y+Z fused ---------
// grid (391, 2). blockIdx.y = ng: CTA computes output cols [ng*64, ng*64+64)
// of BOTH Y (W1) and Z (W2) from ONE A tile. B tile = 128 rows:
//   rows 0..63  -> W1 features ng*64+r (W cols 0..127)
//   rows 64..127-> W2 features ng*64+r (W cols 128..255)
#define GM 128
#define GNB 128                   // B rows per CTA (64 Y + 64 Z)
#define GK 32
#define ROWP 40                   // smem row stride in halves (80B, LDSM conflict-free)
#define A_TILE_B (GM * ROWP * 2)  // 10240 B
#define B_TILE_B (GNB * ROWP * 2) // 10240 B
#define STAGE_B (A_TILE_B + B_TILE_B)            // 20480 B
#define SMEM_TOTAL (4 * STAGE_B)                 // 81920 B (full K prefetch)

__device__ __forceinline__ uint32_t smem_u32(const void* p) {
    uint32_t a;
    asm("{ .reg .u64 t; cvta.to.shared.u64 t, %1; cvt.u32.u64 %0, t; }"
        : "=r"(a) : "l"(p));
    return a;
}

#define LDSM4(r, addr) \
    asm volatile("ldmatrix.sync.aligned.m8n8.x4.shared.b16 {%0,%1,%2,%3}, [%4];" \
                 : "=r"((r)[0]), "=r"((r)[1]), "=r"((r)[2]), "=r"((r)[3])       \
                 : "r"(addr))

__device__ __forceinline__ void mma_fp16(float c[4], const uint32_t a[4],
                                         uint32_t b0, uint32_t b1) {
    asm volatile(
        "mma.sync.aligned.m16n8k16.row.col.f32.f16.f16.f32 "
        "{%0,%1,%2,%3}, {%4,%5,%6,%7}, {%8,%9}, {%0,%1,%2,%3};"
        : "+f"(c[0]), "+f"(c[1]), "+f"(c[2]), "+f"(c[3])
        : "r"(a[0]), "r"(a[1]), "r"(a[2]), "r"(a[3]), "r"(b0), "r"(b1));
}

__device__ __forceinline__ uint32_t offA(int s) { return (uint32_t)(s * STAGE_B); }
__device__ __forceinline__ uint32_t offB(int s) {
    return (uint32_t)(s * STAGE_B + A_TILE_B);
}

// 1024 16B-chunks per stage (A 512, B 512); 4 per thread
__device__ __forceinline__ void load_stage(uint32_t sbase, int s, int k0,
                                           int block_m, int ng, int t) {
#pragma unroll
    for (int j = 0; j < 4; j++) {
        int i = t + j * 256;
        const __half* src;
        uint32_t dst;
        int srcsize = 16;
        if (i < 512) {                        // A tile
            int row = i >> 2;
            int kq = (i & 3) * 8;
            int grow = block_m + row;
            if (grow >= NN) { grow = NN - 1; srcsize = 0; }
            src = g_xh + (size_t)grow * DD + k0 + kq;
            dst = sbase + offA(s) + (uint32_t)((row * ROWP + kq) * 2);
        } else {                              // B tile (128 rows)
            int bi = i - 512;
            int row = bi >> 2;                // 0..127
            int kq = (bi & 3) * 8;
            int feat = ng * 64 + (row & 63);
            int wcol = (row >> 6) * DD;       // 0 -> W1, 128 -> W2
            src = g_wh + (size_t)feat * KK + wcol + k0 + kq;
            dst = sbase + offB(s) + (uint32_t)((row * ROWP + kq) * 2);
        }
        asm volatile("cp.async.cg.shared.global [%0], [%1], 16, %2;"
                     :: "r"(dst), "l"(src), "r"(srcsize));
    }
}

__global__ __launch_bounds__(256, 2)
void gemm_kernel() {
    extern __shared__ char smem[];
    uint32_t sbase = smem_u32(smem);

    int t = threadIdx.x;
    int wid = t >> 5, lane = t & 31;
    int block_m = blockIdx.x * GM;
    int ng = blockIdx.y;                     // output col group
    int wm = (wid & 3) * 32;                 // warp M offset (4 warps)
    int wn = (wid >> 2) * 64;                // warp N offset (2 warps x 64)
    int g = lane >> 2, tig = lane & 3;
    int frow = lane & 15;
    int fcol = (lane >> 4) * 8;

    float acc[2][8][4];
#pragma unroll
    for (int mi = 0; mi < 2; mi++)
#pragma unroll
        for (int ni = 0; ni < 8; ni++)
#pragma unroll
            for (int q = 0; q < 4; q++) acc[mi][ni][q] = 0.f;

    // issue ALL four K stages up front (max MLP)
#pragma unroll
    for (int s = 0; s < 4; s++) {
        load_stage(sbase, s, s * GK, block_m, ng, t);
        asm volatile("cp.async.commit_group;");
    }

#pragma unroll
    for (int kt = 0; kt < 4; kt++) {
        // progressive drain: stage kt complete when <= (3-kt) groups pending
        if (kt == 0)      asm volatile("cp.async.wait_group 3;");
        else if (kt == 1) asm volatile("cp.async.wait_group 2;");
        else if (kt == 2) asm volatile("cp.async.wait_group 1;");
        else              asm volatile("cp.async.wait_group 0;");
        __syncthreads();

        uint32_t aT = sbase + offA(kt);
        uint32_t bT = sbase + offB(kt);

#pragma unroll
        for (int kk16 = 0; kk16 < 2; kk16++) {
            int kk = kk16 * 16;
            uint32_t ah[2][4];
#pragma unroll
            for (int mi = 0; mi < 2; mi++) {
                uint32_t aoff = (uint32_t)(((wm + mi * 16 + frow) * ROWP
                                            + kk + fcol) * 2);
                LDSM4(ah[mi], aT + aoff);
            }
#pragma unroll
            for (int nj = 0; nj < 4; nj++) {
                uint32_t bh[4];
                uint32_t boff = (uint32_t)(((wn + nj * 16 + frow) * ROWP
                                            + kk + fcol) * 2);
                LDSM4(bh, bT + boff);
#pragma unroll
                for (int p = 0; p < 2; p++) {
                    int ni = nj * 2 + p;
#pragma unroll
                    for (int mi = 0; mi < 2; mi++)
                        mma_fp16(acc[mi][ni], ah[mi], bh[p], bh[2 + p]);
                }
            }
        }
    }

    // epilogue: n in [0,128): n<64 -> Y col ng*64+n ; n>=64 -> Z col ng*64+(n-64)
#pragma unroll
    for (int mi = 0; mi < 2; mi++) {
#pragma unroll
        for (int ni = 0; ni < 8; ni++) {
            int n = wn + ni * 8 + 2 * tig;
            __half* dstbase = (n >> 6) ? g_Z : g_Yh;
            int col = ng * 64 + (n & 63);
            int r0 = block_m + wm + mi * 16 + g;
            int r1 = r0 + 8;
            if (r0 < NN)
                *(__half2*)(dstbase + (size_t)r0 * DD + col) =
                    __floats2half2_rn(acc[mi][ni][0], acc[mi][ni][1]);
            if (r1 < NN)
                *(__half2*)(dstbase + (size_t)r1 * DD + col) =
                    __floats2half2_rn(acc[mi][ni][2], acc[mi][ni][3]);
        }
    }
}

// ---------------- 4) fused gather + epilogue ----------------------------------
// out[node] = relu( Yh[node] + b + (sum_{c in bucket} Z[c]) / (cnt + 1e-8) )
__global__ void final_kernel(const float* __restrict__ b, float* __restrict__ out) {
    int gtid = blockIdx.x * blockDim.x + threadIdx.x;
    int node = gtid >> 5;
    int lane = gtid & 31;
    if (node >= NN) return;
    int cnt = g_cnt[node];
    int m = min(cnt, CAP);
    const int* bucket = g_bucket + (size_t)node * CAP;
    float4 acc = make_float4(0.f, 0.f, 0.f, 0.f);
    int c = (m > 0) ? bucket[0] : 0;
    for (int j = 0; j < m; j++) {
        int cn = (j + 1 < m) ? bucket[j + 1] : 0;
        uint2 raw = *(const uint2*)(g_Z + (size_t)c * DD + lane * 4);
        float2 p0 = __half22float2(*(__half2*)&raw.x);
        float2 p1 = __half22float2(*(__half2*)&raw.y);
        acc.x += p0.x; acc.y += p0.y; acc.z += p1.x; acc.w += p1.y;
        c = cn;
    }
    float inv = 1.0f / ((float)cnt + 1e-8f);
    uint2 yraw = *(const uint2*)(g_Yh + (size_t)node * DD + lane * 4);
    float2 y01 = __half22float2(*(__half2*)&yraw.x);
    float2 y23 = __half22float2(*(__half2*)&yraw.y);
    float4 bb = *(const float4*)(b + lane * 4);
    float4 o;
    o.x = fmaxf(y01.x + bb.x + acc.x * inv, 0.f);
    o.y = fmaxf(y01.y + bb.y + acc.y * inv, 0.f);
    o.z = fmaxf(y23.x + bb.z + acc.z * inv, 0.f);
    o.w = fmaxf(y23.y + bb.w + acc.w * inv, 0.f);
    *(float4*)(out + (size_t)node * DOUT + lane * 4) = o;
}

// ---------------- launch ------------------------------------------------------
extern "C" void kernel_launch(void* const* d_in, const int* in_sizes, int n_in,
                              void* d_out, int out_size) {
    const float* x   = (const float*)d_in[0];
    const void*  ei  = d_in[1];
    const float* W   = (const float*)d_in[2];
    const float* b   = (const float*)d_in[3];
    float*       out = (float*)d_out;

    cudaFuncSetAttribute(gemm_kernel,
                         cudaFuncAttributeMaxDynamicSharedMemorySize, SMEM_TOTAL);

    cudaStream_t s1;
    cudaEvent_t  e_fork, e_join;
    cudaStreamCreateWithFlags(&s1, cudaStreamNonBlocking);
    cudaEventCreateWithFlags(&e_fork, cudaEventDisableTiming);
    cudaEventCreateWithFlags(&e_join, cudaEventDisableTiming);

    cudaEventRecord(e_fork, 0);
    cudaStreamWaitEvent(s1, e_fork, 0);

    // adjacency branch (side stream)
    zero_kernel<<<(NN + 255) / 256, 256, 0, s1>>>();
    decode_bucket_kernel<<<(EE + 255) / 256, 256, 0, s1>>>(ei);
    cudaEventRecord(e_join, s1);

    // main stream: fp16 convert then GEMM (overlaps bucket build)
    split_kernel<<<(NX4 + NW4 + 255) / 256, 256>>>(x, W);
    dim3 ggrid((NN + GM - 1) / GM, 2);
    gemm_kernel<<<ggrid, 256, SMEM_TOTAL>>>();

    cudaStreamWaitEvent(0, e_join, 0);
    final_kernel<<<(NN * 32 + 255) / 256, 256>>>(b, out);
}

// round 15
// speedup vs baseline: 1.2694x; 1.2694x over previous
#include <cuda_runtime.h>
#include <cuda_fp16.h>
#include <cstdint>

#define NN 50000
#define EE 640000
#define DD 128          // feature dim (GEMM K)
#define KK 256          // W row length (2*DD)
#define DOUT 128
#define CAP 80          // max neighbors per node (Poisson(12.8): P(>=80) ~ 1e-45)

// ---------------- scratch (static device globals; no allocation) -------------
__device__ __half g_Yh[(size_t)NN * DD];    // x @ W1^T   fp16 (12.8 MB)
__device__ __half g_Z[(size_t)NN * DD];     // x @ W2^T   fp16 (12.8 MB)
__device__ int    g_bucket[(size_t)NN * CAP];  // adjacency buckets (16 MB)
__device__ int    g_cnt[NN];
// fp16 operands
__device__ __half g_xh[(size_t)NN * DD];    // x in fp16 (12.8 MB)
__device__ __half g_wh[DOUT * KK];          // W in fp16

// ---------------- 0) zero counters -------------------------------------------
__global__ void zero_kernel() {
    int i = blockIdx.x * blockDim.x + threadIdx.x;
    if (i < NN) g_cnt[i] = 0;
}

// ---------------- 1) decode edge index + bucket insert (fused) ----------------
__global__ void decode_bucket_kernel(const void* __restrict__ ei) {
    const int* ei32 = (const int*)ei;
    int t = threadIdx.x;
    int accw = ei32[2 * t + 1] | ei32[2 * (t + 256) + 1];
    int is32 = __syncthreads_or(accw);      // nonzero -> int32 indices

    int e = blockIdx.x * blockDim.x + t;
    if (e >= EE) return;
    int r, c;
    if (!is32) {
        const long long* p = (const long long*)ei;
        r = (int)p[e];
        c = (int)p[(size_t)EE + e];
    } else {
        r = ei32[e];
        c = ei32[EE + e];
    }
    r = min(max(r, 0), NN - 1);
    c = min(max(c, 0), NN - 1);
    int slot = atomicAdd(&g_cnt[r], 1);
    if (slot < CAP)
        g_bucket[(size_t)r * CAP + slot] = c;
}

// ---------------- 2) one-pass fp16 convert of x and W -------------------------
#define NX4 ((NN * DD) / 4)
#define NW4 ((DOUT * KK) / 4)
__global__ void split_kernel(const float* __restrict__ x, const float* __restrict__ W) {
    int i = blockIdx.x * blockDim.x + threadIdx.x;
    if (i < NX4) {
        float4 v = ((const float4*)x)[i];
        __half2 h01 = __floats2half2_rn(v.x, v.y);
        __half2 h23 = __floats2half2_rn(v.z, v.w);
        uint2 pk;
        pk.x = *(uint32_t*)&h01;
        pk.y = *(uint32_t*)&h23;
        *(uint2*)(g_xh + (size_t)i * 4) = pk;
    } else if (i < NX4 + NW4) {
        int j = i - NX4;
        float4 v = ((const float4*)W)[j];
        __half2 h01 = __floats2half2_rn(v.x, v.y);
        __half2 h23 = __floats2half2_rn(v.z, v.w);
        uint2 pk;
        pk.x = *(uint32_t*)&h01;
        pk.y = *(uint32_t*)&h23;
        *(uint2*)(g_wh + (size_t)j * 4) = pk;
    }
}

// ---------------- 3) GEMM via fp16 mma.sync + ldmatrix + cp.async -------------
// [Y|Z] = x @ [W1;W2]^T, single-term fp16 (fp32 accumulate), fp16 outputs.
// CTA tile 128(M) x 64(N); grid = (391, 4): blockIdx.y = {half, ngroup}.
// (round-13 proven config: 2-stage, 3 CTA/SM, regs ~72)
#define GM 128
#define GN 64
#define GK 32
#define ROWP 40                   // smem row stride in halves (80B, LDSM conflict-free)
#define A_TILE_B (GM * ROWP * 2)  // 10240 B per 128x32 fp16 tile
#define B_TILE_B (GN * ROWP * 2)  // 5120 B per 64x32 fp16 tile
#define STAGE_B (A_TILE_B + B_TILE_B)            // 15360 B
#define SMEM_TOTAL (2 * STAGE_B)                 // 30720 B

__device__ __forceinline__ uint32_t smem_u32(const void* p) {
    uint32_t a;
    asm("{ .reg .u64 t; cvta.to.shared.u64 t, %1; cvt.u32.u64 %0, t; }"
        : "=r"(a) : "l"(p));
    return a;
}

#define LDSM4(r, addr) \
    asm volatile("ldmatrix.sync.aligned.m8n8.x4.shared.b16 {%0,%1,%2,%3}, [%4];" \
                 : "=r"((r)[0]), "=r"((r)[1]), "=r"((r)[2]), "=r"((r)[3])       \
                 : "r"(addr))

__device__ __forceinline__ void mma_fp16(float c[4], const uint32_t a[4],
                                         uint32_t b0, uint32_t b1) {
    asm volatile(
        "mma.sync.aligned.m16n8k16.row.col.f32.f16.f16.f32 "
        "{%0,%1,%2,%3}, {%4,%5,%6,%7}, {%8,%9}, {%0,%1,%2,%3};"
        : "+f"(c[0]), "+f"(c[1]), "+f"(c[2]), "+f"(c[3])
        : "r"(a[0]), "r"(a[1]), "r"(a[2]), "r"(a[3]), "r"(b0), "r"(b1));
}

__device__ __forceinline__ uint32_t offA(int s) { return (uint32_t)(s * STAGE_B); }
__device__ __forceinline__ uint32_t offB(int s) {
    return (uint32_t)(s * STAGE_B + A_TILE_B);
}

// 768 16B-chunks per stage: A 512, B 256; 3 per thread
// wbias = halfsel*DD + brow0*KK  (column offset + feature-row offset combined)
__device__ __forceinline__ void load_stage(uint32_t sbase, int s, int k0,
                                           int block_m, int wbias, int t) {
#pragma unroll
    for (int j = 0; j < 3; j++) {
        int i = t + j * 256;
        const __half* src;
        uint32_t dst;
        int srcsize = 16;
        if (i < 512) {                        // A tile
            int row = i >> 2;
            int kq = (i & 3) * 8;
            int grow = block_m + row;
            if (grow >= NN) { grow = NN - 1; srcsize = 0; }
            src = g_xh + (size_t)grow * DD + k0 + kq;
            dst = sbase + offA(s) + (uint32_t)((row * ROWP + kq) * 2);
        } else {                              // B tile
            int bi = i - 512;
            int row = bi >> 2;
            int kq = (bi & 3) * 8;
            src = g_wh + (size_t)row * KK + wbias + k0 + kq;
            dst = sbase + offB(s) + (uint32_t)((row * ROWP + kq) * 2);
        }
        asm volatile("cp.async.cg.shared.global [%0], [%1], 16, %2;"
                     :: "r"(dst), "l"(src), "r"(srcsize));
    }
}

__global__ __launch_bounds__(256, 3)
void gemm_kernel() {
    extern __shared__ char smem[];
    uint32_t sbase = smem_u32(smem);

    int t = threadIdx.x;
    int wid = t >> 5, lane = t & 31;
    int block_m = blockIdx.x * GM;
    int halfsel = blockIdx.y >> 1;           // 0 -> Y (W1), 1 -> Z (W2)
    int ng = blockIdx.y & 1;                 // which 64-feature group
    int brow0 = ng * GN;
    int wbias = halfsel * DD + brow0 * KK;   // combined W offset
    int wm = (wid & 3) * 32;
    int wn = (wid >> 2) * 32;
    int g = lane >> 2, tig = lane & 3;
    int frow = lane & 15;
    int fcol = (lane >> 4) * 8;

    float acc[2][4][4];
#pragma unroll
    for (int mi = 0; mi < 2; mi++)
#pragma unroll
        for (int ni = 0; ni < 4; ni++)
#pragma unroll
            for (int q = 0; q < 4; q++) acc[mi][ni][q] = 0.f;

    load_stage(sbase, 0, 0, block_m, wbias, t);
    asm volatile("cp.async.commit_group;");

#pragma unroll
    for (int kt = 0; kt < 4; kt++) {
        int s = kt & 1;
        if (kt < 3) {
            load_stage(sbase, s ^ 1, (kt + 1) * GK, block_m, wbias, t);
            asm volatile("cp.async.commit_group;");
            asm volatile("cp.async.wait_group 1;");
        } else {
            asm volatile("cp.async.wait_group 0;");
        }
        __syncthreads();

        uint32_t aT = sbase + offA(s);
        uint32_t bT = sbase + offB(s);

#pragma unroll
        for (int kk16 = 0; kk16 < 2; kk16++) {
            int kk = kk16 * 16;
            uint32_t ah[2][4];
#pragma unroll
            for (int mi = 0; mi < 2; mi++) {
                uint32_t aoff = (uint32_t)(((wm + mi * 16 + frow) * ROWP
                                            + kk + fcol) * 2);
                LDSM4(ah[mi], aT + aoff);
            }
#pragma unroll
            for (int nj = 0; nj < 2; nj++) {
                uint32_t bh[4];
                uint32_t boff = (uint32_t)(((wn + nj * 16 + frow) * ROWP
                                            + kk + fcol) * 2);
                LDSM4(bh, bT + boff);
#pragma unroll
                for (int p = 0; p < 2; p++) {
                    int ni = nj * 2 + p;
#pragma unroll
                    for (int mi = 0; mi < 2; mi++)
                        mma_fp16(acc[mi][ni], ah[mi], bh[p], bh[2 + p]);
                }
            }
        }
        __syncthreads();
    }

    // epilogue: fp16 stores for both Y and Z
    __half* dstbase = halfsel ? g_Z : g_Yh;
#pragma unroll
    for (int mi = 0; mi < 2; mi++) {
#pragma unroll
        for (int ni = 0; ni < 4; ni++) {
            int r0 = block_m + wm + mi * 16 + g;
            int r1 = r0 + 8;
            int n = brow0 + wn + ni * 8 + 2 * tig;
            if (r0 < NN)
                *(__half2*)(dstbase + (size_t)r0 * DD + n) =
                    __floats2half2_rn(acc[mi][ni][0], acc[mi][ni][1]);
            if (r1 < NN)
                *(__half2*)(dstbase + (size_t)r1 * DD + n) =
                    __floats2half2_rn(acc[mi][ni][2], acc[mi][ni][3]);
        }
    }
}

// ---------------- 4) fused gather + epilogue ----------------------------------
// out[node] = relu( Yh[node] + b + (sum_{c in bucket} Z[c]) / (cnt + 1e-8) )
__global__ void final_kernel(const float* __restrict__ b, float* __restrict__ out) {
    int gtid = blockIdx.x * blockDim.x + threadIdx.x;
    int node = gtid >> 5;
    int lane = gtid & 31;
    if (node >= NN) return;
    int cnt = g_cnt[node];
    int m = min(cnt, CAP);
    const int* bucket = g_bucket + (size_t)node * CAP;
    float4 acc = make_float4(0.f, 0.f, 0.f, 0.f);
    int c = (m > 0) ? bucket[0] : 0;
    for (int j = 0; j < m; j++) {
        int cn = (j + 1 < m) ? bucket[j + 1] : 0;
        uint2 raw = *(const uint2*)(g_Z + (size_t)c * DD + lane * 4);
        float2 p0 = __half22float2(*(__half2*)&raw.x);
        float2 p1 = __half22float2(*(__half2*)&raw.y);
        acc.x += p0.x; acc.y += p0.y; acc.z += p1.x; acc.w += p1.y;
        c = cn;
    }
    float inv = 1.0f / ((float)cnt + 1e-8f);
    uint2 yraw = *(const uint2*)(g_Yh + (size_t)node * DD + lane * 4);
    float2 y01 = __half22float2(*(__half2*)&yraw.x);
    float2 y23 = __half22float2(*(__half2*)&yraw.y);
    float4 bb = *(const float4*)(b + lane * 4);
    float4 o;
    o.x = fmaxf(y01.x + bb.x + acc.x * inv, 0.f);
    o.y = fmaxf(y01.y + bb.y + acc.y * inv, 0.f);
    o.z = fmaxf(y23.x + bb.z + acc.z * inv, 0.f);
    o.w = fmaxf(y23.y + bb.w + acc.w * inv, 0.f);
    *(float4*)(out + (size_t)node * DOUT + lane * 4) = o;
}

// ---------------- launch ------------------------------------------------------
extern "C" void kernel_launch(void* const* d_in, const int* in_sizes, int n_in,
                              void* d_out, int out_size) {
    const float* x   = (const float*)d_in[0];
    const void*  ei  = d_in[1];
    const float* W   = (const float*)d_in[2];
    const float* b   = (const float*)d_in[3];
    float*       out = (float*)d_out;

    cudaFuncSetAttribute(gemm_kernel,
                         cudaFuncAttributeMaxDynamicSharedMemorySize, SMEM_TOTAL);

    cudaStream_t s1;
    cudaEvent_t  e_fork, e_join;
    cudaStreamCreateWithFlags(&s1, cudaStreamNonBlocking);
    cudaEventCreateWithFlags(&e_fork, cudaEventDisableTiming);
    cudaEventCreateWithFlags(&e_join, cudaEventDisableTiming);

    cudaEventRecord(e_fork, 0);
    cudaStreamWaitEvent(s1, e_fork, 0);

    // adjacency branch (side stream)
    zero_kernel<<<(NN + 255) / 256, 256, 0, s1>>>();
    decode_bucket_kernel<<<(EE + 255) / 256, 256, 0, s1>>>(ei);
    cudaEventRecord(e_join, s1);

    // main stream: fp16 convert then GEMM (overlaps bucket build)
    split_kernel<<<(NX4 + NW4 + 255) / 256, 256>>>(x, W);
    dim3 ggrid((NN + GM - 1) / GM, 4);
    gemm_kernel<<<ggrid, 256, SMEM_TOTAL>>>();

    cudaStreamWaitEvent(0, e_join, 0);
    final_kernel<<<(NN * 32 + 255) / 256, 256>>>(b, out);
}

// round 16
// speedup vs baseline: 1.3757x; 1.0837x over previous
#include <cuda_runtime.h>
#include <cuda_fp16.h>
#include <cstdint>

#define NN 50000
#define EE 640000
#define DD 128          // feature dim (GEMM K)
#define KK 256          // W row length (2*DD)
#define DOUT 128
#define CAP 80          // max neighbors per node (Poisson(12.8): P(>=80) ~ 1e-45)

// ---------------- scratch (static device globals; no allocation) -------------
__device__ __half g_Yh[(size_t)NN * DD];    // x @ W1^T   fp16 (12.8 MB)
__device__ __half g_Z[(size_t)NN * DD];     // x @ W2^T   fp16 (12.8 MB)
__device__ int    g_bucket[(size_t)NN * CAP];  // adjacency buckets (16 MB)
__device__ int    g_cnt[NN];
// fp16 operands
__device__ __half g_xh[(size_t)NN * DD];    // x in fp16 (12.8 MB)
__device__ __half g_wh[DOUT * KK];          // W in fp16

// ---------------- 0) zero counters -------------------------------------------
__global__ void zero_kernel() {
    int i = blockIdx.x * blockDim.x + threadIdx.x;
    if (i < NN) g_cnt[i] = 0;
}

// ---------------- 1) decode edge index + bucket insert (fused) ----------------
__global__ void decode_bucket_kernel(const void* __restrict__ ei) {
    const int* ei32 = (const int*)ei;
    int t = threadIdx.x;
    int accw = ei32[2 * t + 1] | ei32[2 * (t + 256) + 1];
    int is32 = __syncthreads_or(accw);      // nonzero -> int32 indices

    int e = blockIdx.x * blockDim.x + t;
    if (e >= EE) return;
    int r, c;
    if (!is32) {
        const long long* p = (const long long*)ei;
        r = (int)p[e];
        c = (int)p[(size_t)EE + e];
    } else {
        r = ei32[e];
        c = ei32[EE + e];
    }
    r = min(max(r, 0), NN - 1);
    c = min(max(c, 0), NN - 1);
    int slot = atomicAdd(&g_cnt[r], 1);
    if (slot < CAP)
        g_bucket[(size_t)r * CAP + slot] = c;
}

// ---------------- 2) one-pass fp16 convert of x and W -------------------------
#define NX4 ((NN * DD) / 4)
#define NW4 ((DOUT * KK) / 4)
__global__ void split_kernel(const float* __restrict__ x, const float* __restrict__ W) {
    int i = blockIdx.x * blockDim.x + threadIdx.x;
    if (i < NX4) {
        float4 v = ((const float4*)x)[i];
        __half2 h01 = __floats2half2_rn(v.x, v.y);
        __half2 h23 = __floats2half2_rn(v.z, v.w);
        uint2 pk;
        pk.x = *(uint32_t*)&h01;
        pk.y = *(uint32_t*)&h23;
        *(uint2*)(g_xh + (size_t)i * 4) = pk;
    } else if (i < NX4 + NW4) {
        int j = i - NX4;
        float4 v = ((const float4*)W)[j];
        __half2 h01 = __floats2half2_rn(v.x, v.y);
        __half2 h23 = __floats2half2_rn(v.z, v.w);
        uint2 pk;
        pk.x = *(uint32_t*)&h01;
        pk.y = *(uint32_t*)&h23;
        *(uint2*)(g_wh + (size_t)j * 4) = pk;
    }
}

// ---------------- 3) GEMM: fp16 mma.sync, A-resident, Y+Z sequential ----------
// grid (391, 2). blockIdx.y = ng (output col group of 64).
// Each CTA: loads full A[128x128] once; 8 B stages (half in {Y,Z} x kt in 0..3)
// stream through a 4-slot ring; acc (32 fp32) reused across halves.
#define GM 128
#define GN 64
#define GK 32
#define ROWP 40                   // smem row stride in halves (80B, LDSM conflict-free)
#define A_CHUNK_B (GM * ROWP * 2) // 10240 B per 128x32 chunk
#define B_TILE_B (GN * ROWP * 2)  // 5120 B per 64x32 tile
#define A_ALL_B (4 * A_CHUNK_B)   // 40960 B
#define SMEM_TOTAL (A_ALL_B + 4 * B_TILE_B)   // 61440 B

__device__ __forceinline__ uint32_t smem_u32(const void* p) {
    uint32_t a;
    asm("{ .reg .u64 t; cvta.to.shared.u64 t, %1; cvt.u32.u64 %0, t; }"
        : "=r"(a) : "l"(p));
    return a;
}

#define LDSM4(r, addr) \
    asm volatile("ldmatrix.sync.aligned.m8n8.x4.shared.b16 {%0,%1,%2,%3}, [%4];" \
                 : "=r"((r)[0]), "=r"((r)[1]), "=r"((r)[2]), "=r"((r)[3])       \
                 : "r"(addr))

__device__ __forceinline__ void mma_fp16(float c[4], const uint32_t a[4],
                                         uint32_t b0, uint32_t b1) {
    asm volatile(
        "mma.sync.aligned.m16n8k16.row.col.f32.f16.f16.f32 "
        "{%0,%1,%2,%3}, {%4,%5,%6,%7}, {%8,%9}, {%0,%1,%2,%3};"
        : "+f"(c[0]), "+f"(c[1]), "+f"(c[2]), "+f"(c[3])
        : "r"(a[0]), "r"(a[1]), "r"(a[2]), "r"(a[3]), "r"(b0), "r"(b1));
}

// B stage load: 256 chunks of 16B, one per thread.
// stage s: half = s>>2, kt = s&3, slot = s&3.
__device__ __forceinline__ void load_b(uint32_t sbase, int s, int ng, int t) {
    int half = s >> 2;
    int kt = s & 3;
    int row = t >> 2;                 // 0..63
    int kq = (t & 3) * 8;
    const __half* src = g_wh + (size_t)(ng * GN + row) * KK + half * DD
                        + kt * GK + kq;
    uint32_t dst = sbase + A_ALL_B + (uint32_t)((s & 3) * B_TILE_B
                                                + (row * ROWP + kq) * 2);
    asm volatile("cp.async.cg.shared.global [%0], [%1], 16;"
                 :: "r"(dst), "l"(src));
}

__global__ __launch_bounds__(256, 3)
void gemm_kernel() {
    extern __shared__ char smem[];
    uint32_t sbase = smem_u32(smem);

    int t = threadIdx.x;
    int wid = t >> 5, lane = t & 31;
    int block_m = blockIdx.x * GM;
    int ng = blockIdx.y;
    int wm = (wid & 3) * 32;
    int wn = (wid >> 2) * 32;
    int g = lane >> 2, tig = lane & 3;
    int frow = lane & 15;
    int fcol = (lane >> 4) * 8;

    // ---- group 0: full A (8 chunks/thread) + B stage 0 ----
#pragma unroll
    for (int j = 0; j < 8; j++) {
        int i = t + j * 256;
        int chunk = i >> 9;               // 0..3 (k chunk)
        int idx = i & 511;
        int row = idx >> 2;
        int kq = (idx & 3) * 8;
        int grow = block_m + row;
        int srcsize = 16;
        if (grow >= NN) { grow = NN - 1; srcsize = 0; }
        const __half* src = g_xh + (size_t)grow * DD + chunk * GK + kq;
        uint32_t dst = sbase + (uint32_t)(chunk * A_CHUNK_B
                                          + (row * ROWP + kq) * 2);
        asm volatile("cp.async.cg.shared.global [%0], [%1], 16, %2;"
                     :: "r"(dst), "l"(src), "r"(srcsize));
    }
    load_b(sbase, 0, ng, t);
    asm volatile("cp.async.commit_group;");
    // ---- groups 1..3: B stages 1..3 ----
#pragma unroll
    for (int s = 1; s < 4; s++) {
        load_b(sbase, s, ng, t);
        asm volatile("cp.async.commit_group;");
    }

    float acc[2][4][4];
#pragma unroll
    for (int mi = 0; mi < 2; mi++)
#pragma unroll
        for (int ni = 0; ni < 4; ni++)
#pragma unroll
            for (int q = 0; q < 4; q++) acc[mi][ni][q] = 0.f;

#pragma unroll
    for (int s = 0; s < 8; s++) {
        // wait for stage s (groups complete in order; see pipeline accounting)
        if (s < 5)      asm volatile("cp.async.wait_group 3;");
        else if (s == 5) asm volatile("cp.async.wait_group 2;");
        else if (s == 6) asm volatile("cp.async.wait_group 1;");
        else             asm volatile("cp.async.wait_group 0;");
        __syncthreads();

        uint32_t aT = sbase + (uint32_t)((s & 3) * A_CHUNK_B);
        uint32_t bT = sbase + A_ALL_B + (uint32_t)((s & 3) * B_TILE_B);

#pragma unroll
        for (int kk16 = 0; kk16 < 2; kk16++) {
            int kk = kk16 * 16;
            uint32_t ah[2][4];
#pragma unroll
            for (int mi = 0; mi < 2; mi++) {
                uint32_t aoff = (uint32_t)(((wm + mi * 16 + frow) * ROWP
                                            + kk + fcol) * 2);
                LDSM4(ah[mi], aT + aoff);
            }
#pragma unroll
            for (int nj = 0; nj < 2; nj++) {
                uint32_t bh[4];
                uint32_t boff = (uint32_t)(((wn + nj * 16 + frow) * ROWP
                                            + kk + fcol) * 2);
                LDSM4(bh, bT + boff);
#pragma unroll
                for (int p = 0; p < 2; p++) {
                    int ni = nj * 2 + p;
#pragma unroll
                    for (int mi = 0; mi < 2; mi++)
                        mma_fp16(acc[mi][ni], ah[mi], bh[p], bh[2 + p]);
                }
            }
        }
        __syncthreads();                    // done reading slot s&3

        if (s + 4 < 8) {                    // refill slot with stage s+4
            load_b(sbase, s + 4, ng, t);
            asm volatile("cp.async.commit_group;");
        }

        if (s == 3 || s == 7) {             // end of a half: store, reset acc
            __half* dstbase = (s == 3) ? g_Yh : g_Z;
#pragma unroll
            for (int mi = 0; mi < 2; mi++) {
#pragma unroll
                for (int ni = 0; ni < 4; ni++) {
                    int r0 = block_m + wm + mi * 16 + g;
                    int r1 = r0 + 8;
                    int n = ng * GN + wn + ni * 8 + 2 * tig;
                    if (r0 < NN)
                        *(__half2*)(dstbase + (size_t)r0 * DD + n) =
                            __floats2half2_rn(acc[mi][ni][0], acc[mi][ni][1]);
                    if (r1 < NN)
                        *(__half2*)(dstbase + (size_t)r1 * DD + n) =
                            __floats2half2_rn(acc[mi][ni][2], acc[mi][ni][3]);
                    acc[mi][ni][0] = acc[mi][ni][1] = 0.f;
                    acc[mi][ni][2] = acc[mi][ni][3] = 0.f;
                }
            }
        }
    }
}

// ---------------- 4) fused gather + epilogue ----------------------------------
// out[node] = relu( Yh[node] + b + (sum_{c in bucket} Z[c]) / (cnt + 1e-8) )
__global__ void final_kernel(const float* __restrict__ b, float* __restrict__ out) {
    int gtid = blockIdx.x * blockDim.x + threadIdx.x;
    int node = gtid >> 5;
    int lane = gtid & 31;
    if (node >= NN) return;
    int cnt = g_cnt[node];
    int m = min(cnt, CAP);
    const int* bucket = g_bucket + (size_t)node * CAP;
    float4 acc = make_float4(0.f, 0.f, 0.f, 0.f);
    int c = (m > 0) ? bucket[0] : 0;
    for (int j = 0; j < m; j++) {
        int cn = (j + 1 < m) ? bucket[j + 1] : 0;
        uint2 raw = *(const uint2*)(g_Z + (size_t)c * DD + lane * 4);
        float2 p0 = __half22float2(*(__half2*)&raw.x);
        float2 p1 = __half22float2(*(__half2*)&raw.y);
        acc.x += p0.x; acc.y += p0.y; acc.z += p1.x; acc.w += p1.y;
        c = cn;
    }
    float inv = 1.0f / ((float)cnt + 1e-8f);
    uint2 yraw = *(const uint2*)(g_Yh + (size_t)node * DD + lane * 4);
    float2 y01 = __half22float2(*(__half2*)&yraw.x);
    float2 y23 = __half22float2(*(__half2*)&yraw.y);
    float4 bb = *(const float4*)(b + lane * 4);
    float4 o;
    o.x = fmaxf(y01.x + bb.x + acc.x * inv, 0.f);
    o.y = fmaxf(y01.y + bb.y + acc.y * inv, 0.f);
    o.z = fmaxf(y23.x + bb.z + acc.z * inv, 0.f);
    o.w = fmaxf(y23.y + bb.w + acc.w * inv, 0.f);
    *(float4*)(out + (size_t)node * DOUT + lane * 4) = o;
}

// ---------------- launch ------------------------------------------------------
extern "C" void kernel_launch(void* const* d_in, const int* in_sizes, int n_in,
                              void* d_out, int out_size) {
    const float* x   = (const float*)d_in[0];
    const void*  ei  = d_in[1];
    const float* W   = (const float*)d_in[2];
    const float* b   = (const float*)d_in[3];
    float*       out = (float*)d_out;

    cudaFuncSetAttribute(gemm_kernel,
                         cudaFuncAttributeMaxDynamicSharedMemorySize, SMEM_TOTAL);

    cudaStream_t s1;
    cudaEvent_t  e_fork, e_join;
    cudaStreamCreateWithFlags(&s1, cudaStreamNonBlocking);
    cudaEventCreateWithFlags(&e_fork, cudaEventDisableTiming);
    cudaEventCreateWithFlags(&e_join, cudaEventDisableTiming);

    cudaEventRecord(e_fork, 0);
    cudaStreamWaitEvent(s1, e_fork, 0);

    // adjacency branch (side stream)
    zero_kernel<<<(NN + 255) / 256, 256, 0, s1>>>();
    decode_bucket_kernel<<<(EE + 255) / 256, 256, 0, s1>>>(ei);
    cudaEventRecord(e_join, s1);

    // main stream: fp16 convert then GEMM (overlaps bucket build)
    split_kernel<<<(NX4 + NW4 + 255) / 256, 256>>>(x, W);
    dim3 ggrid((NN + GM - 1) / GM, 2);
    gemm_kernel<<<ggrid, 256, SMEM_TOTAL>>>();

    cudaStreamWaitEvent(0, e_join, 0);
    final_kernel<<<(NN * 32 + 255) / 256, 256>>>(b, out);
}

// round 17
// speedup vs baseline: 1.4091x; 1.0243x over previous
#include <cuda_runtime.h>
#include <cuda_fp16.h>
#include <cstdint>

#define NN 50000
#define EE 640000
#define DD 128          // feature dim (GEMM K)
#define KK 256          // W row length (2*DD)
#define DOUT 128
#define CAP 80          // max neighbors per node (Poisson(12.8): P(>=80) ~ 1e-45)

// ---------------- scratch (static device globals; no allocation) -------------
__device__ __half g_Yh[(size_t)NN * DD];    // x @ W1^T   fp16 (12.8 MB)
__device__ __half g_Z[(size_t)NN * DD];     // x @ W2^T   fp16 (12.8 MB)
__device__ int    g_bucket[(size_t)NN * CAP];  // adjacency buckets (16 MB)
__device__ int    g_cnt[NN];
__device__ __half g_wh[DOUT * KK];          // W in fp16

// ---------------- 0) zero counters -------------------------------------------
__global__ void zero_kernel() {
    int i = blockIdx.x * blockDim.x + threadIdx.x;
    if (i < NN) g_cnt[i] = 0;
}

// ---------------- 1) decode edge index + bucket insert (fused) ----------------
__global__ void decode_bucket_kernel(const void* __restrict__ ei) {
    const int* ei32 = (const int*)ei;
    int t = threadIdx.x;
    int accw = ei32[2 * t + 1] | ei32[2 * (t + 256) + 1];
    int is32 = __syncthreads_or(accw);      // nonzero -> int32 indices

    int e = blockIdx.x * blockDim.x + t;
    if (e >= EE) return;
    int r, c;
    if (!is32) {
        const long long* p = (const long long*)ei;
        r = (int)p[e];
        c = (int)p[(size_t)EE + e];
    } else {
        r = ei32[e];
        c = ei32[EE + e];
    }
    r = min(max(r, 0), NN - 1);
    c = min(max(c, 0), NN - 1);
    int slot = atomicAdd(&g_cnt[r], 1);
    if (slot < CAP)
        g_bucket[(size_t)r * CAP + slot] = c;
}

// ---------------- 2) W -> fp16 (tiny; 32K elements) ---------------------------
#define NW4 ((DOUT * KK) / 4)
__global__ void wconv_kernel(const float* __restrict__ W) {
    int j = blockIdx.x * blockDim.x + threadIdx.x;
    if (j < NW4) {
        float4 v = ((const float4*)W)[j];
        __half2 h01 = __floats2half2_rn(v.x, v.y);
        __half2 h23 = __floats2half2_rn(v.z, v.w);
        uint2 pk;
        pk.x = *(uint32_t*)&h01;
        pk.y = *(uint32_t*)&h23;
        *(uint2*)(g_wh + (size_t)j * 4) = pk;
    }
}

// ---------------- 3) GEMM: fp16 mma.sync, in-kernel A convert -----------------
// grid (391, 2). blockIdx.y = ng (output col group of 64).
// Prologue: issue 4 B cp.async stages, then LDG fp32 x rows -> cvt -> STS fp16
// into the resident A region (overlaps with B transfers). 8 B stages
// (half in {Y,Z} x kt in 0..3) stream through a 4-slot ring.
#define GM 128
#define GN 64
#define GK 32
#define ROWP 40                   // smem row stride in halves (80B, LDSM conflict-free)
#define A_CHUNK_B (GM * ROWP * 2) // 10240 B per 128x32 chunk
#define B_TILE_B (GN * ROWP * 2)  // 5120 B per 64x32 tile
#define A_ALL_B (4 * A_CHUNK_B)   // 40960 B
#define SMEM_TOTAL (A_ALL_B + 4 * B_TILE_B)   // 61440 B

__device__ __forceinline__ uint32_t smem_u32(const void* p) {
    uint32_t a;
    asm("{ .reg .u64 t; cvta.to.shared.u64 t, %1; cvt.u32.u64 %0, t; }"
        : "=r"(a) : "l"(p));
    return a;
}

#define LDSM4(r, addr) \
    asm volatile("ldmatrix.sync.aligned.m8n8.x4.shared.b16 {%0,%1,%2,%3}, [%4];" \
                 : "=r"((r)[0]), "=r"((r)[1]), "=r"((r)[2]), "=r"((r)[3])       \
                 : "r"(addr))

__device__ __forceinline__ void mma_fp16(float c[4], const uint32_t a[4],
                                         uint32_t b0, uint32_t b1) {
    asm volatile(
        "mma.sync.aligned.m16n8k16.row.col.f32.f16.f16.f32 "
        "{%0,%1,%2,%3}, {%4,%5,%6,%7}, {%8,%9}, {%0,%1,%2,%3};"
        : "+f"(c[0]), "+f"(c[1]), "+f"(c[2]), "+f"(c[3])
        : "r"(a[0]), "r"(a[1]), "r"(a[2]), "r"(a[3]), "r"(b0), "r"(b1));
}

// B stage load: 256 chunks of 16B, one per thread.
// stage s: half = s>>2, kt = s&3, slot = s&3.
__device__ __forceinline__ void load_b(uint32_t sbase, int s, int ng, int t) {
    int half = s >> 2;
    int kt = s & 3;
    int row = t >> 2;                 // 0..63
    int kq = (t & 3) * 8;
    const __half* src = g_wh + (size_t)(ng * GN + row) * KK + half * DD
                        + kt * GK + kq;
    uint32_t dst = sbase + A_ALL_B + (uint32_t)((s & 3) * B_TILE_B
                                                + (row * ROWP + kq) * 2);
    asm volatile("cp.async.cg.shared.global [%0], [%1], 16;"
                 :: "r"(dst), "l"(src));
}

__global__ __launch_bounds__(256, 3)
void gemm_kernel(const float* __restrict__ x) {
    extern __shared__ char smem[];
    uint32_t sbase = smem_u32(smem);

    int t = threadIdx.x;
    int wid = t >> 5, lane = t & 31;
    int block_m = blockIdx.x * GM;
    int ng = blockIdx.y;
    int wm = (wid & 3) * 32;
    int wn = (wid >> 2) * 32;
    int g = lane >> 2, tig = lane & 3;
    int frow = lane & 15;
    int fcol = (lane >> 4) * 8;

    // ---- B stages 0..3 via cp.async (4 groups) ----
#pragma unroll
    for (int s = 0; s < 4; s++) {
        load_b(sbase, s, ng, t);
        asm volatile("cp.async.commit_group;");
    }

    // ---- A prologue: LDG fp32 x -> cvt -> STS fp16 (overlaps B transfers) ----
    // 4096 float4 chunks; 16/thread. 32 lanes cover one 128-float row.
#pragma unroll
    for (int j = 0; j < 16; j++) {
        int i4 = t + j * 256;             // float4 index
        int row = i4 >> 5;                // 0..127
        int col4 = (i4 & 31) * 4;         // 0..124
        int grow = block_m + row;
        float4 v = make_float4(0.f, 0.f, 0.f, 0.f);
        if (grow < NN)
            v = *(const float4*)(x + (size_t)grow * DD + col4);
        __half2 h01 = __floats2half2_rn(v.x, v.y);
        __half2 h23 = __floats2half2_rn(v.z, v.w);
        uint2 pk;
        pk.x = *(uint32_t*)&h01;
        pk.y = *(uint32_t*)&h23;
        int chunk = col4 >> 5;
        int kq = col4 & 31;
        *(uint2*)(smem + chunk * A_CHUNK_B + (row * ROWP + kq) * 2) = pk;
    }

    float acc[2][4][4];
#pragma unroll
    for (int mi = 0; mi < 2; mi++)
#pragma unroll
        for (int ni = 0; ni < 4; ni++)
#pragma unroll
            for (int q = 0; q < 4; q++) acc[mi][ni][q] = 0.f;

#pragma unroll
    for (int s = 0; s < 8; s++) {
        // B group drain schedule (stages complete in commit order)
        if (s < 5)       asm volatile("cp.async.wait_group 3;");
        else if (s == 5) asm volatile("cp.async.wait_group 2;");
        else if (s == 6) asm volatile("cp.async.wait_group 1;");
        else             asm volatile("cp.async.wait_group 0;");
        __syncthreads();   // also orders the A-convert STS (s==0)

        uint32_t aT = sbase + (uint32_t)((s & 3) * A_CHUNK_B);
        uint32_t bT = sbase + A_ALL_B + (uint32_t)((s & 3) * B_TILE_B);

#pragma unroll
        for (int kk16 = 0; kk16 < 2; kk16++) {
            int kk = kk16 * 16;
            uint32_t ah[2][4];
#pragma unroll
            for (int mi = 0; mi < 2; mi++) {
                uint32_t aoff = (uint32_t)(((wm + mi * 16 + frow) * ROWP
                                            + kk + fcol) * 2);
                LDSM4(ah[mi], aT + aoff);
            }
#pragma unroll
            for (int nj = 0; nj < 2; nj++) {
                uint32_t bh[4];
                uint32_t boff = (uint32_t)(((wn + nj * 16 + frow) * ROWP
                                            + kk + fcol) * 2);
                LDSM4(bh, bT + boff);
#pragma unroll
                for (int p = 0; p < 2; p++) {
                    int ni = nj * 2 + p;
#pragma unroll
                    for (int mi = 0; mi < 2; mi++)
                        mma_fp16(acc[mi][ni], ah[mi], bh[p], bh[2 + p]);
                }
            }
        }
        __syncthreads();                    // done reading B slot s&3

        if (s + 4 < 8) {                    // refill slot with stage s+4
            load_b(sbase, s + 4, ng, t);
            asm volatile("cp.async.commit_group;");
        }

        if (s == 3 || s == 7) {             // end of a half: store, reset acc
            __half* dstbase = (s == 3) ? g_Yh : g_Z;
#pragma unroll
            for (int mi = 0; mi < 2; mi++) {
#pragma unroll
                for (int ni = 0; ni < 4; ni++) {
                    int r0 = block_m + wm + mi * 16 + g;
                    int r1 = r0 + 8;
                    int n = ng * GN + wn + ni * 8 + 2 * tig;
                    if (r0 < NN)
                        *(__half2*)(dstbase + (size_t)r0 * DD + n) =
                            __floats2half2_rn(acc[mi][ni][0], acc[mi][ni][1]);
                    if (r1 < NN)
                        *(__half2*)(dstbase + (size_t)r1 * DD + n) =
                            __floats2half2_rn(acc[mi][ni][2], acc[mi][ni][3]);
                    acc[mi][ni][0] = acc[mi][ni][1] = 0.f;
                    acc[mi][ni][2] = acc[mi][ni][3] = 0.f;
                }
            }
        }
    }
}

// ---------------- 4) fused gather + epilogue ----------------------------------
// out[node] = relu( Yh[node] + b + (sum_{c in bucket} Z[c]) / (cnt + 1e-8) )
__global__ void final_kernel(const float* __restrict__ b, float* __restrict__ out) {
    int gtid = blockIdx.x * blockDim.x + threadIdx.x;
    int node = gtid >> 5;
    int lane = gtid & 31;
    if (node >= NN) return;
    int cnt = g_cnt[node];
    int m = min(cnt, CAP);
    const int* bucket = g_bucket + (size_t)node * CAP;
    float4 acc = make_float4(0.f, 0.f, 0.f, 0.f);
    int c = (m > 0) ? bucket[0] : 0;
    for (int j = 0; j < m; j++) {
        int cn = (j + 1 < m) ? bucket[j + 1] : 0;
        uint2 raw = *(const uint2*)(g_Z + (size_t)c * DD + lane * 4);
        float2 p0 = __half22float2(*(__half2*)&raw.x);
        float2 p1 = __half22float2(*(__half2*)&raw.y);
        acc.x += p0.x; acc.y += p0.y; acc.z += p1.x; acc.w += p1.y;
        c = cn;
    }
    float inv = 1.0f / ((float)cnt + 1e-8f);
    uint2 yraw = *(const uint2*)(g_Yh + (size_t)node * DD + lane * 4);
    float2 y01 = __half22float2(*(__half2*)&yraw.x);
    float2 y23 = __half22float2(*(__half2*)&yraw.y);
    float4 bb = *(const float4*)(b + lane * 4);
    float4 o;
    o.x = fmaxf(y01.x + bb.x + acc.x * inv, 0.f);
    o.y = fmaxf(y01.y + bb.y + acc.y * inv, 0.f);
    o.z = fmaxf(y23.x + bb.z + acc.z * inv, 0.f);
    o.w = fmaxf(y23.y + bb.w + acc.w * inv, 0.f);
    *(float4*)(out + (size_t)node * DOUT + lane * 4) = o;
}

// ---------------- launch ------------------------------------------------------
extern "C" void kernel_launch(void* const* d_in, const int* in_sizes, int n_in,
                              void* d_out, int out_size) {
    const float* x   = (const float*)d_in[0];
    const void*  ei  = d_in[1];
    const float* W   = (const float*)d_in[2];
    const float* b   = (const float*)d_in[3];
    float*       out = (float*)d_out;

    cudaFuncSetAttribute(gemm_kernel,
                         cudaFuncAttributeMaxDynamicSharedMemorySize, SMEM_TOTAL);

    cudaStream_t s1;
    cudaEvent_t  e_fork, e_join;
    cudaStreamCreateWithFlags(&s1, cudaStreamNonBlocking);
    cudaEventCreateWithFlags(&e_fork, cudaEventDisableTiming);
    cudaEventCreateWithFlags(&e_join, cudaEventDisableTiming);

    cudaEventRecord(e_fork, 0);
    cudaStreamWaitEvent(s1, e_fork, 0);

    // adjacency branch (side stream)
    zero_kernel<<<(NN + 255) / 256, 256, 0, s1>>>();
    decode_bucket_kernel<<<(EE + 255) / 256, 256, 0, s1>>>(ei);
    cudaEventRecord(e_join, s1);

    // main stream: tiny W convert then GEMM (A converts in-kernel)
    wconv_kernel<<<(NW4 + 255) / 256, 256>>>(W);
    dim3 ggrid((NN + GM - 1) / GM, 2);
    gemm_kernel<<<ggrid, 256, SMEM_TOTAL>>>(x);

    cudaStreamWaitEvent(0, e_join, 0);
    final_kernel<<<(NN * 32 + 255) / 256, 256>>>(b, out);
}